// round 3
// baseline (speedup 1.0000x reference)
#include <cuda_runtime.h>
#include <cstdint>

#define D        32
#define D_ANCIL  16
#define DIN      80      // 2*D + D_ANCIL
#define HID      128
#define GRID_G   64
#define NN       4096    // GRID_G*GRID_G
#define BB       8
#define TOTAL    (BB*NN) // 32768 nodes
#define ROW      80      // floats per node row in (B,N,80)

// ---- packed f32x2 helpers (sm_100+ PTX; ptxas will not auto-fuse these) ----
#define FMA2(d, a, b, c) \
    asm("fma.rn.f32x2 %0, %1, %2, %3;" : "=l"(d) : "l"(a), "l"(b), "l"(c))
#define ADD2(d, a, b) \
    asm("add.rn.f32x2 %0, %1, %2;" : "=l"(d) : "l"(a), "l"(b))
#define PACK2(d, lo, hi) \
    asm("mov.b64 %0, {%1, %2};" : "=l"(d) : "f"(lo), "f"(hi))
#define UNPACK2(lo, hi, s) \
    asm("mov.b64 {%0, %1}, %2;" : "=f"(lo), "=f"(hi) : "l"(s))

__device__ __forceinline__ float tanh_fast(float x) {
    // tanh(x) = 1 - 2/(exp(2x)+1). MUFU-based, ~2^-22 rel err, correct saturation.
    float e = __expf(x + x);
    return 1.0f - __fdividef(2.0f, e + 1.0f);
}

// One half-update: z_tgt += dt_b * F(z_src, xi).
// TWO threads per node (lane pair 2m / 2m+1):
//   even lane: input half = [ z(32) | xi(0:8) ]        (k-dims 0..31, 64..71)
//   odd  lane: input half = [ mean_nbr(32) | xi(8:16) ] (k-dims 32..63, 72..79)
// Partial h_j combined via shfl_xor(1); W2 output dim split 16/16 per lane.
// W1 staged in smem transposed+permuted: W1s[j][0:40]=even half, [40:80]=odd half.
__global__ void __launch_bounds__(128, 5)
half_step_kernel(float* __restrict__ state,
                 const float* __restrict__ tfin,
                 const float* __restrict__ W1,   // (80,128) k-major, j contiguous
                 const float* __restrict__ b1,   // (128)
                 const float* __restrict__ W2,   // (128,32) j-major, d contiguous
                 const float* __restrict__ b2,   // (32)
                 int zoff, int toff,
                 float tstart, float dtmax)
{
    extern __shared__ __align__(16) float smem[];
    float* W1s = smem;              // [j][dst] : 128*80 floats (41 KB)
    float* b1s = W1s + HID * DIN;   // [j]

    const int tid = threadIdx.x;

    // Stage W1: transpose [k][j] -> [j][dst(k)] with half-permutation:
    //   k in [0,32):  dst = k        (even half: z)
    //   k in [32,64): dst = k + 8    (odd half: mean)  -> 40..71
    //   k in [64,72): dst = k - 32   (even half: xi lo) -> 32..39
    //   k in [72,80): dst = k        (odd half: xi hi)  -> 72..79
    for (int idx = tid; idx < HID * DIN; idx += 128) {
        int k = idx >> 7;           // 0..79
        int j = idx & 127;          // 0..127
        int dst = (k < 32) ? k : (k < 64 ? k + 8 : (k < 72 ? k - 32 : k));
        W1s[j * DIN + dst] = W1[idx];
    }
    if (tid < HID) b1s[tid] = b1[tid];

    const int g    = blockIdx.x * 128 + tid;  // 0..65535
    const int node = g >> 1;                  // 0..32767
    const int half = g & 1;                   // 0 even / 1 odd
    const int b = node >> 12;
    const int n = node & (NN - 1);
    const int r = n >> 6, c = n & (GRID_G - 1);
    const int nu = (((r + GRID_G - 1) & (GRID_G - 1)) << 6) | c;
    const int nd = (((r + 1) & (GRID_G - 1)) << 6) | c;
    const int nl = (r << 6) | ((c + GRID_G - 1) & (GRID_G - 1));
    const int nr = (r << 6) | ((c + 1) & (GRID_G - 1));

    const float* bp = state + (size_t)b * NN * ROW;
    // Divergence-free gather: even lane points all 4 at its own row;
    // 0.25*(z+z+z+z) == z bitwise (exact in fp32).
    const float4* pA = (const float4*)(bp + (size_t)(half ? nu : n) * ROW + zoff);
    const float4* pB = (const float4*)(bp + (size_t)(half ? nd : n) * ROW + zoff);
    const float4* pC = (const float4*)(bp + (size_t)(half ? nl : n) * ROW + zoff);
    const float4* pD = (const float4*)(bp + (size_t)(half ? nr : n) * ROW + zoff);

    unsigned long long xp[20];
    #pragma unroll
    for (int i = 0; i < 8; i++) {
        float4 a = pA[i], d2 = pB[i], e = pC[i], f = pD[i];
        float vx = 0.25f * (a.x + d2.x + e.x + f.x);
        float vy = 0.25f * (a.y + d2.y + e.y + f.y);
        float vz = 0.25f * (a.z + d2.z + e.z + f.z);
        float vw = 0.25f * (a.w + d2.w + e.w + f.w);
        PACK2(xp[2 * i],     vx, vy);
        PACK2(xp[2 * i + 1], vz, vw);
    }
    {   // xi slice: even lane gets xi[0:8], odd gets xi[8:16]
        const float4* pX = (const float4*)(bp + (size_t)n * ROW + 2 * D + half * 8);
        float4 x0 = pX[0], x1 = pX[1];
        PACK2(xp[16], x0.x, x0.y);
        PACK2(xp[17], x0.z, x0.w);
        PACK2(xp[18], x1.x, x1.y);
        PACK2(xp[19], x1.z, x1.w);
    }

    // output accumulators: this lane's 16 of 32 outputs, init with b2 slice
    unsigned long long oacc[8];
    {
        const float4* b2v = (const float4*)(b2 + half * 16);
        #pragma unroll
        for (int i = 0; i < 4; i++) {
            float4 v = b2v[i];
            PACK2(oacc[2 * i],     v.x, v.y);
            PACK2(oacc[2 * i + 1], v.z, v.w);
        }
    }

    __syncthreads();

    #pragma unroll 2
    for (int j = 0; j < HID; j++) {
        const ulonglong2* wp =
            reinterpret_cast<const ulonglong2*>(W1s + j * DIN + half * 40);
        unsigned long long a0 = 0ull, a1 = 0ull, a2 = 0ull, a3 = 0ull;
        // 40 floats = 20 pairs = 10 ulonglong2
        #pragma unroll
        for (int u = 0; u < 10; u += 2) {
            ulonglong2 w0 = wp[u];
            ulonglong2 w1 = wp[u + 1];
            FMA2(a0, xp[2 * u],     w0.x, a0);
            FMA2(a1, xp[2 * u + 1], w0.y, a1);
            FMA2(a2, xp[2 * u + 2], w1.x, a2);
            FMA2(a3, xp[2 * u + 3], w1.y, a3);
        }
        ADD2(a0, a0, a1);
        ADD2(a2, a2, a3);
        ADD2(a0, a0, a2);
        float lo, hi;
        UNPACK2(lo, hi, a0);
        float sh = lo + hi;
        float so = __shfl_xor_sync(0xffffffffu, sh, 1);
        float s = sh + so + b1s[j];
        float t = tanh_fast(s);
        unsigned long long tt;
        PACK2(tt, t, t);

        // W2 slice from global (L1-resident, 16 KB, uniform per lane parity)
        const ulonglong2* w2p =
            reinterpret_cast<const ulonglong2*>(W2 + j * D + half * 16);
        #pragma unroll
        for (int u = 0; u < 4; u++) {
            ulonglong2 w = __ldg(w2p + u);
            FMA2(oacc[2 * u],     tt, w.x, oacc[2 * u]);
            FMA2(oacc[2 * u + 1], tt, w.y, oacc[2 * u + 1]);
        }
    }

    // dt = clip(tf - tstart, 0, dtmax), per batch (exact fp32 schedule)
    float tfv = tfin[b];
    float dtv = fminf(fmaxf(tfv - tstart, 0.0f), dtmax);

    float* tgt = state + (size_t)b * NN * ROW + (size_t)n * ROW + toff + half * 16;
    #pragma unroll
    for (int u = 0; u < 4; u++) {
        float4 cur = *(float4*)(tgt + 4 * u);
        float o0, o1, o2, o3;
        UNPACK2(o0, o1, oacc[2 * u]);
        UNPACK2(o2, o3, oacc[2 * u + 1]);
        cur.x += dtv * o0;
        cur.y += dtv * o1;
        cur.z += dtv * o2;
        cur.w += dtv * o3;
        *(float4*)(tgt + 4 * u) = cur;
    }
}

extern "C" void kernel_launch(void* const* d_in, const int* in_sizes, int n_in,
                              void* d_out, int out_size)
{
    const float* x    = (const float*)d_in[0];
    const float* tf   = (const float*)d_in[1];
    const float* W1q  = (const float*)d_in[2];
    const float* b1q  = (const float*)d_in[3];
    const float* W2q  = (const float*)d_in[4];
    const float* b2q  = (const float*)d_in[5];
    const float* W1p  = (const float*)d_in[6];
    const float* b1p  = (const float*)d_in[7];
    const float* W2p  = (const float*)d_in[8];
    const float* b2p  = (const float*)d_in[9];
    float* state = (float*)d_out;

    const int smem = (HID * DIN + HID) * (int)sizeof(float); // 41472 B
    cudaFuncSetAttribute(half_step_kernel,
                         cudaFuncAttributeMaxDynamicSharedMemorySize, smem);

    // state := x   (q,p,xi all copied; xi stays valid for the final output)
    cudaMemcpyAsync(state, x, (size_t)out_size * sizeof(float),
                    cudaMemcpyDeviceToDevice);

    const int blocks = (2 * TOTAL) / 128; // 512
    const float DT = 0.25f;

    for (int k = 0; k < 18; k++) {
        // q-phase: reads p (zoff=32), writes q (toff=0)
        float tsq = (k == 0) ? 0.0f : (0.125f + (k - 1) * DT);
        float dmq = (k == 0) ? 0.125f : DT;
        half_step_kernel<<<blocks, 128, smem>>>(
            state, tf, W1q, b1q, W2q, b2q, /*zoff=*/D, /*toff=*/0, tsq, dmq);

        // p-phase: reads q (zoff=0), writes p (toff=32)
        float tsp = k * DT;
        half_step_kernel<<<blocks, 128, smem>>>(
            state, tf, W1p, b1p, W2p, b2p, /*zoff=*/0, /*toff=*/D, tsp, DT);
    }
    (void)in_sizes; (void)n_in;
}

// round 4
// speedup vs baseline: 1.2640x; 1.2640x over previous
#include <cuda_runtime.h>
#include <cstdint>

#define D        32
#define D_ANCIL  16
#define HID      128
#define GRID_G   64
#define NN       4096
#define BB       8
#define TOTAL    (BB*NN)   // 32768 nodes
#define ROW      80        // floats per node row in (B,N,80)

// W1 smem: per j, 64 floats; rows (j, j+64) interleaved in 136-float pairs,
// odd half at +68 floats (272B == 16 mod 128 -> no bank conflict vs even).
#define W1_PAIR   136
#define W1_ODD    68
// W2 smem: per j, 32 floats; pair stride 72, odd at +36 (144B == 16 mod 128).
#define W2_PAIR   72
#define W2_ODD    36
#define SMEM_W1   (64 * W1_PAIR)            // 8704 floats
#define SMEM_W2   (64 * W2_PAIR)            // 4608 floats
#define SMEM_FLT  (SMEM_W1 + SMEM_W2)       // 13312 floats = 53248 B

// xi-contribution scratch: C[net][node][j]
__device__ float g_C[2][TOTAL * HID];

// ---- packed f32x2 helpers ----
#define FMA2(d, a, b, c) \
    asm("fma.rn.f32x2 %0, %1, %2, %3;" : "=l"(d) : "l"(a), "l"(b), "l"(c))
#define ADD2(d, a, b) \
    asm("add.rn.f32x2 %0, %1, %2;" : "=l"(d) : "l"(a), "l"(b))
#define PACK2(d, lo, hi) \
    asm("mov.b64 %0, {%1, %2};" : "=l"(d) : "f"(lo), "f"(hi))
#define UNPACK2(lo, hi, s) \
    asm("mov.b64 {%0, %1}, %2;" : "=f"(lo), "=f"(hi) : "l"(s))

__device__ __forceinline__ float tanh_fast(float x) {
    float e = __expf(x + x);
    return 1.0f - __fdividef(2.0f, e + 1.0f);
}

// ---------------------------------------------------------------------------
// Precompute C[which][n][j] = b1[j] + sum_k xi[n][k] * W1[64+k][j]
// xi = x[..., 64:80] is constant over all steps.
// ---------------------------------------------------------------------------
__global__ void __launch_bounds__(128)
precompute_C_kernel(const float* __restrict__ x,
                    const float* __restrict__ W1,
                    const float* __restrict__ b1,
                    int which)
{
    __shared__ float W1cs[16 * HID];  // [j][k], 8KB
    __shared__ float b1s[HID];
    const int tid = threadIdx.x;
    for (int idx = tid; idx < 16 * HID; idx += 128) {
        int k = idx >> 7, j = idx & 127;
        W1cs[j * 16 + k] = W1[(64 + k) * HID + j];
    }
    if (tid < HID) b1s[tid] = b1[tid];
    __syncthreads();

    const int n = blockIdx.x * 128 + tid;          // 0..32767
    const float4* xiv = (const float4*)(x + (size_t)n * ROW + 2 * D);
    unsigned long long xp8[8];
    #pragma unroll
    for (int i = 0; i < 4; i++) {
        float4 v = xiv[i];
        PACK2(xp8[2 * i],     v.x, v.y);
        PACK2(xp8[2 * i + 1], v.z, v.w);
    }
    float* Crow = g_C[which] + (size_t)n * HID;
    for (int jb = 0; jb < 32; jb++) {
        float s[4];
        #pragma unroll
        for (int jj = 0; jj < 4; jj++) {
            int j = jb * 4 + jj;
            const ulonglong2* wp = (const ulonglong2*)(W1cs + j * 16);
            unsigned long long a0 = 0ull, a1 = 0ull;
            #pragma unroll
            for (int u = 0; u < 4; u++) {
                ulonglong2 w = wp[u];
                FMA2(a0, xp8[2 * u],     w.x, a0);
                FMA2(a1, xp8[2 * u + 1], w.y, a1);
            }
            ADD2(a0, a0, a1);
            float lo, hi;
            UNPACK2(lo, hi, a0);
            s[jj] = lo + hi + b1s[j];
        }
        *(float4*)(Crow + jb * 4) = make_float4(s[0], s[1], s[2], s[3]);
    }
}

// ---------------------------------------------------------------------------
// Half-update: z_tgt += dt * F(z_src, xi).  2 threads/node, split over j:
//   half=0 -> j in [0,64),  half=1 -> j in [64,128).
// Both threads build the full 64-dim input [z | mean_nbr] in registers;
// each accumulates the full 32-dim output over its j-half; one shfl at end.
// ---------------------------------------------------------------------------
__global__ void __launch_bounds__(128, 4)
half_step_kernel(float* __restrict__ state,
                 const float* __restrict__ tfin,
                 const float* __restrict__ W1,   // (80,128) k-major
                 const float* __restrict__ W2,   // (128,32) j-major
                 const float* __restrict__ b2,   // (32)
                 int which,                      // C selector
                 int zoff, int toff,
                 float tstart, float dtmax)
{
    extern __shared__ __align__(16) float smem[];
    float* W1s = smem;             // interleaved pairs, 8704 floats
    float* W2s = smem + SMEM_W1;   // interleaved pairs, 4608 floats

    const int tid = threadIdx.x;

    // Stage W1 rows k<64 transposed: dst row for global j is
    // (j&63)*136 + (j>>6)*68, element k at +k.
    for (int idx = tid; idx < 64 * HID; idx += 128) {
        int k = idx >> 7, j = idx & 127;
        W1s[(j & 63) * W1_PAIR + (j >> 6) * W1_ODD + k] = W1[idx];
    }
    // Stage W2: row for j at (j&63)*72 + (j>>6)*36.
    for (int idx = tid; idx < HID * D; idx += 128) {
        int j = idx >> 5, d = idx & 31;
        W2s[(j & 63) * W2_PAIR + (j >> 6) * W2_ODD + d] = W2[idx];
    }

    const int g    = blockIdx.x * 128 + tid;   // 0..65535
    const int node = g >> 1;
    const int half = g & 1;
    const int b = node >> 12;
    const int n = node & (NN - 1);
    const int r = n >> 6, c = n & (GRID_G - 1);
    const int nu = (((r + GRID_G - 1) & (GRID_G - 1)) << 6) | c;
    const int nd = (((r + 1) & (GRID_G - 1)) << 6) | c;
    const int nl = (r << 6) | ((c + GRID_G - 1) & (GRID_G - 1));
    const int nr = (r << 6) | ((c + 1) & (GRID_G - 1));

    const float* bp = state + (size_t)b * NN * ROW;
    const float4* pZ = (const float4*)(bp + (size_t)n  * ROW + zoff);
    const float4* pU = (const float4*)(bp + (size_t)nu * ROW + zoff);
    const float4* pD = (const float4*)(bp + (size_t)nd * ROW + zoff);
    const float4* pL = (const float4*)(bp + (size_t)nl * ROW + zoff);
    const float4* pR = (const float4*)(bp + (size_t)nr * ROW + zoff);

    // xp pairs 0..15 = own z, 16..31 = neighbour mean.
    unsigned long long xp[32];
    #pragma unroll
    for (int i = 0; i < 8; i++) {
        float4 o = pZ[i];
        float4 u = pU[i], d2 = pD[i], e = pL[i], f = pR[i];
        PACK2(xp[2 * i],     o.x, o.y);
        PACK2(xp[2 * i + 1], o.z, o.w);
        float mx = 0.25f * (u.x + d2.x + e.x + f.x);
        float my = 0.25f * (u.y + d2.y + e.y + f.y);
        float mz = 0.25f * (u.z + d2.z + e.z + f.z);
        float mw = 0.25f * (u.w + d2.w + e.w + f.w);
        PACK2(xp[16 + 2 * i],     mx, my);
        PACK2(xp[16 + 2 * i + 1], mz, mw);
    }

    // oacc: full 32 outputs; even lane seeds with b2, odd with 0.
    unsigned long long oacc[16];
    {
        float hsel = half ? 0.0f : 1.0f;
        const float4* b2v = (const float4*)b2;
        #pragma unroll
        for (int i = 0; i < 8; i++) {
            float4 v = __ldg(b2v + i);
            PACK2(oacc[2 * i],     v.x * hsel, v.y * hsel);
            PACK2(oacc[2 * i + 1], v.z * hsel, v.w * hsel);
        }
    }

    const float* Crow = g_C[which] + ((size_t)node << 7) + (half << 6);
    const float* W1base = W1s + half * W1_ODD;
    const float* W2base = W2s + half * W2_ODD;

    __syncthreads();

    for (int jb = 0; jb < 16; jb++) {
        float4 c4 = __ldg((const float4*)(Crow + jb * 4));
        float s[4];
        #pragma unroll
        for (int jj = 0; jj < 4; jj++) {
            const ulonglong2* wp = (const ulonglong2*)
                (W1base + (jb * 4 + jj) * W1_PAIR);
            unsigned long long a0 = 0ull, a1 = 0ull, a2 = 0ull, a3 = 0ull;
            #pragma unroll
            for (int u = 0; u < 16; u += 2) {
                ulonglong2 w0 = wp[u];
                ulonglong2 w1 = wp[u + 1];
                FMA2(a0, xp[2 * u],     w0.x, a0);
                FMA2(a1, xp[2 * u + 1], w0.y, a1);
                FMA2(a2, xp[2 * u + 2], w1.x, a2);
                FMA2(a3, xp[2 * u + 3], w1.y, a3);
            }
            ADD2(a0, a0, a1);
            ADD2(a2, a2, a3);
            ADD2(a0, a0, a2);
            float lo, hi;
            UNPACK2(lo, hi, a0);
            s[jj] = lo + hi;
        }
        s[0] = tanh_fast(s[0] + c4.x);
        s[1] = tanh_fast(s[1] + c4.y);
        s[2] = tanh_fast(s[2] + c4.z);
        s[3] = tanh_fast(s[3] + c4.w);
        #pragma unroll
        for (int jj = 0; jj < 4; jj++) {
            unsigned long long tt;
            PACK2(tt, s[jj], s[jj]);
            const ulonglong2* w2p = (const ulonglong2*)
                (W2base + (jb * 4 + jj) * W2_PAIR);
            #pragma unroll
            for (int u = 0; u < 8; u++) {
                ulonglong2 w = w2p[u];
                FMA2(oacc[2 * u],     tt, w.x, oacc[2 * u]);
                FMA2(oacc[2 * u + 1], tt, w.y, oacc[2 * u + 1]);
            }
        }
    }

    // Combine j-halves: even keeps outputs [0:16), odd keeps [16:32).
    #pragma unroll
    for (int u = 0; u < 8; u++) {
        unsigned long long send = half ? oacc[u] : oacc[u + 8];
        unsigned long long got = __shfl_xor_sync(0xffffffffu, send, 1);
        int dst = u + 8 * half;
        ADD2(oacc[dst], oacc[dst], got);
    }

    float tfv = tfin[b];
    float dtv = fminf(fmaxf(tfv - tstart, 0.0f), dtmax);

    float* tgt = state + (size_t)b * NN * ROW + (size_t)n * ROW + toff
               + half * 16;
    #pragma unroll
    for (int u = 0; u < 4; u++) {
        float4 cur = *(float4*)(tgt + 4 * u);
        float o0, o1, o2, o3;
        UNPACK2(o0, o1, oacc[8 * half + 2 * u]);
        UNPACK2(o2, o3, oacc[8 * half + 2 * u + 1]);
        cur.x += dtv * o0;
        cur.y += dtv * o1;
        cur.z += dtv * o2;
        cur.w += dtv * o3;
        *(float4*)(tgt + 4 * u) = cur;
    }
}

extern "C" void kernel_launch(void* const* d_in, const int* in_sizes, int n_in,
                              void* d_out, int out_size)
{
    const float* x    = (const float*)d_in[0];
    const float* tf   = (const float*)d_in[1];
    const float* W1q  = (const float*)d_in[2];
    const float* b1q  = (const float*)d_in[3];
    const float* W2q  = (const float*)d_in[4];
    const float* b2q  = (const float*)d_in[5];
    const float* W1p  = (const float*)d_in[6];
    const float* b1p  = (const float*)d_in[7];
    const float* W2p  = (const float*)d_in[8];
    const float* b2p  = (const float*)d_in[9];
    float* state = (float*)d_out;

    const int smem = SMEM_FLT * (int)sizeof(float);  // 53248 B
    cudaFuncSetAttribute(half_step_kernel,
                         cudaFuncAttributeMaxDynamicSharedMemorySize, smem);

    cudaMemcpyAsync(state, x, (size_t)out_size * sizeof(float),
                    cudaMemcpyDeviceToDevice);

    // xi contributions, constant over all steps
    precompute_C_kernel<<<TOTAL / 128, 128>>>(x, W1q, b1q, 0);
    precompute_C_kernel<<<TOTAL / 128, 128>>>(x, W1p, b1p, 1);

    const int blocks = (2 * TOTAL) / 128;  // 512
    const float DT = 0.25f;

    for (int k = 0; k < 18; k++) {
        float tsq = (k == 0) ? 0.0f : (0.125f + (k - 1) * DT);
        float dmq = (k == 0) ? 0.125f : DT;
        half_step_kernel<<<blocks, 128, smem>>>(
            state, tf, W1q, W2q, b2q, /*which=*/0,
            /*zoff=*/D, /*toff=*/0, tsq, dmq);

        float tsp = k * DT;
        half_step_kernel<<<blocks, 128, smem>>>(
            state, tf, W1p, W2p, b2p, /*which=*/1,
            /*zoff=*/0, /*toff=*/D, tsp, DT);
    }
    (void)in_sizes; (void)n_in;
}

// round 5
// speedup vs baseline: 1.8603x; 1.4718x over previous
#include <cuda_runtime.h>
#include <cstdint>

#define D        32
#define HID      128
#define GRID_G   64
#define NN       4096
#define BB       8
#define TOTAL    (BB*NN)   // 32768 nodes
#define ROW      80        // floats per node row
#define NT       32        // nodes per CTA
#define XSTR     68        // X smem row stride (floats), 272B: 16B-aligned rows

// xi-contribution scratch: C[net][node][j] (includes b1)
__device__ float g_C[2][TOTAL * HID];

// ---- packed f32x2 helpers ----
#define FMA2(d, a, b, c) \
    asm("fma.rn.f32x2 %0, %1, %2, %3;" : "=l"(d) : "l"(a), "l"(b), "l"(c))
#define ADD2(d, a, b) \
    asm("add.rn.f32x2 %0, %1, %2;" : "=l"(d) : "l"(a), "l"(b))
#define PACK2(d, lo, hi) \
    asm("mov.b64 %0, {%1, %2};" : "=l"(d) : "f"(lo), "f"(hi))
#define UNPACK2(lo, hi, s) \
    asm("mov.b64 {%0, %1}, %2;" : "=f"(lo), "=f"(hi) : "l"(s))

__device__ __forceinline__ float tanh_fast(float x) {
    float e = __expf(x + x);
    return 1.0f - __fdividef(2.0f, e + 1.0f);
}

// ---------------------------------------------------------------------------
// Precompute C[which][n][j] = b1[j] + sum_k xi[n][k] * W1[64+k][j]
// ---------------------------------------------------------------------------
__global__ void __launch_bounds__(128)
precompute_C_kernel(const float* __restrict__ x,
                    const float* __restrict__ W1,
                    const float* __restrict__ b1,
                    int which)
{
    __shared__ float W1cs[16 * HID];  // [j][k]
    __shared__ float b1s[HID];
    const int tid = threadIdx.x;
    for (int idx = tid; idx < 16 * HID; idx += 128) {
        int k = idx >> 7, j = idx & 127;
        W1cs[j * 16 + k] = W1[(64 + k) * HID + j];
    }
    if (tid < HID) b1s[tid] = b1[tid];
    __syncthreads();

    const int n = blockIdx.x * 128 + tid;
    const float4* xiv = (const float4*)(x + (size_t)n * ROW + 2 * D);
    unsigned long long xp8[8];
    #pragma unroll
    for (int i = 0; i < 4; i++) {
        float4 v = xiv[i];
        PACK2(xp8[2 * i],     v.x, v.y);
        PACK2(xp8[2 * i + 1], v.z, v.w);
    }
    float* Crow = g_C[which] + (size_t)n * HID;
    for (int jb = 0; jb < 32; jb++) {
        float s[4];
        #pragma unroll
        for (int jj = 0; jj < 4; jj++) {
            int j = jb * 4 + jj;
            const ulonglong2* wp = (const ulonglong2*)(W1cs + j * 16);
            unsigned long long a0 = 0ull, a1 = 0ull;
            #pragma unroll
            for (int u = 0; u < 4; u++) {
                ulonglong2 w = wp[u];
                FMA2(a0, xp8[2 * u],     w.x, a0);
                FMA2(a1, xp8[2 * u + 1], w.y, a1);
            }
            ADD2(a0, a0, a1);
            float lo, hi;
            UNPACK2(lo, hi, a0);
            s[jj] = lo + hi + b1s[j];
        }
        *(float4*)(Crow + jb * 4) = make_float4(s[0], s[1], s[2], s[3]);
    }
}

// ---------------------------------------------------------------------------
// Half-update, weight-stationary:
//   Phase G: gather X[n] = [z(32) | mean_nbr(32)] into smem (4 thr/node).
//   Phase A: thread t holds W1[:,t] in regs; h[n][t] = tanh(dot + C[n][t]).
//            x reads are warp-uniform broadcasts (free-ish).
//   Phase B: warp w holds W2[j-quarter w][:, lane] in regs; strip-rotated
//            accumulation into two smem partial buffers.
//   Final:  out[n][d]: z += dt * (P0 + P1 + b2[d]).
// ---------------------------------------------------------------------------
__global__ void __launch_bounds__(128, 4)
half_step_kernel(float* __restrict__ state,
                 const float* __restrict__ tfin,
                 const float* __restrict__ W1,   // (80,128) k-major
                 const float* __restrict__ W2,   // (128,32) j-major
                 const float* __restrict__ b2,   // (32)
                 int which,
                 int zoff, int toff,
                 float tstart, float dtmax)
{
    __shared__ float Xs[NT * XSTR];      // 2176 floats
    __shared__ float Hs[NT * HID];       // 4096 floats
    __shared__ float Ps[2 * NT * D];     // 2048 floats

    const int tid = threadIdx.x;
    const int node_base = blockIdx.x * NT;

    // ---- Phase A weight load (global, coalesced over lanes) ----
    const int j = tid;
    unsigned long long w1p[32];
    #pragma unroll
    for (int i = 0; i < 32; i++)
        PACK2(w1p[i], W1[(2 * i) * HID + j], W1[(2 * i + 1) * HID + j]);

    // ---- Phase G: gather ----
    {
        const int n    = tid >> 2;       // 0..31
        const int part = tid & 3;
        const int node = node_base + n;
        const int nn_  = node & (NN - 1);
        const int r = nn_ >> 6, c = nn_ & (GRID_G - 1);
        const float* rowbase = state + (size_t)(node - nn_) * ROW; // batch base

        if (part < 2) {
            const float4* src = (const float4*)
                (state + (size_t)node * ROW + zoff + part * 16);
            float4* dst = (float4*)(Xs + n * XSTR + part * 16);
            #pragma unroll
            for (int i = 0; i < 4; i++) dst[i] = src[i];
        } else {
            const int nu = (((r + GRID_G - 1) & (GRID_G - 1)) << 6) | c;
            const int nd = (((r + 1) & (GRID_G - 1)) << 6) | c;
            const int nl = (r << 6) | ((c + GRID_G - 1) & (GRID_G - 1));
            const int nr = (r << 6) | ((c + 1) & (GRID_G - 1));
            const int koff = (part - 2) * 16;
            const float4* pu = (const float4*)(rowbase + (size_t)nu * ROW + zoff + koff);
            const float4* pd = (const float4*)(rowbase + (size_t)nd * ROW + zoff + koff);
            const float4* pl = (const float4*)(rowbase + (size_t)nl * ROW + zoff + koff);
            const float4* pr = (const float4*)(rowbase + (size_t)nr * ROW + zoff + koff);
            float4* dst = (float4*)(Xs + n * XSTR + 32 + koff);
            #pragma unroll
            for (int i = 0; i < 4; i++) {
                float4 a = pu[i], b = pd[i], e = pl[i], f = pr[i];
                float4 m;
                m.x = 0.25f * (a.x + b.x + e.x + f.x);
                m.y = 0.25f * (a.y + b.y + e.y + f.y);
                m.z = 0.25f * (a.z + b.z + e.z + f.z);
                m.w = 0.25f * (a.w + b.w + e.w + f.w);
                dst[i] = m;
            }
        }
    }
    __syncthreads();

    // ---- Phase A: GEMM1 + tanh, weights in regs, x broadcast from smem ----
    {
        const float* Crow = g_C[which] + (size_t)node_base * HID + j;
        #pragma unroll 2
        for (int n = 0; n < NT; n++) {
            float cv = __ldg(Crow + n * HID);
            const ulonglong2* xr = (const ulonglong2*)(Xs + n * XSTR);
            unsigned long long a0 = 0ull, a1 = 0ull, a2 = 0ull, a3 = 0ull;
            #pragma unroll
            for (int i = 0; i < 16; i += 2) {
                ulonglong2 u = xr[i];
                ulonglong2 v = xr[i + 1];
                FMA2(a0, u.x, w1p[2 * i],     a0);
                FMA2(a1, u.y, w1p[2 * i + 1], a1);
                FMA2(a2, v.x, w1p[2 * i + 2], a2);
                FMA2(a3, v.y, w1p[2 * i + 3], a3);
            }
            ADD2(a0, a0, a1);
            ADD2(a2, a2, a3);
            ADD2(a0, a0, a2);
            float lo, hi;
            UNPACK2(lo, hi, a0);
            Hs[n * HID + j] = tanh_fast(lo + hi + cv);
        }
    }
    __syncthreads();

    // ---- Phase B: GEMM2, W2 quarter in regs, strip rotation ----
    {
        const int dlane = tid & 31;
        const int w     = tid >> 5;      // j-quarter
        const int pb    = w >> 1;        // partial buffer

        unsigned long long w2p[16];
        #pragma unroll
        for (int i = 0; i < 16; i++) {
            int jj = w * 32 + 2 * i;
            PACK2(w2p[i], W2[jj * D + dlane], W2[(jj + 1) * D + dlane]);
        }

        for (int s = 0; s < 2; s++) {
            const int st = (w + s) & 1;
            const int n0 = st * 16;
            #pragma unroll 2
            for (int n = n0; n < n0 + 16; n++) {
                const ulonglong2* hr =
                    (const ulonglong2*)(Hs + n * HID + w * 32);
                unsigned long long a0 = 0ull, a1 = 0ull;
                #pragma unroll
                for (int i = 0; i < 8; i += 2) {
                    ulonglong2 u = hr[i];
                    ulonglong2 v = hr[i + 1];
                    FMA2(a0, u.x, w2p[2 * i],     a0);
                    FMA2(a1, u.y, w2p[2 * i + 1], a1);
                    FMA2(a0, v.x, w2p[2 * i + 2], a0);
                    FMA2(a1, v.y, w2p[2 * i + 3], a1);
                }
                ADD2(a0, a0, a1);
                float lo, hi;
                UNPACK2(lo, hi, a0);
                float val = lo + hi;
                float* pp = Ps + pb * (NT * D) + n * D + dlane;
                if (s == 0) *pp = val;
                else        *pp += val;
            }
            __syncthreads();
        }
    }

    // ---- Final: z += dt * (P0 + P1 + b2) ----
    {
        const int bcta = node_base >> 12;
        float tfv = __ldg(tfin + bcta);
        float dtv = fminf(fmaxf(tfv - tstart, 0.0f), dtmax);
        #pragma unroll
        for (int rix = 0; rix < 8; rix++) {
            int idx = rix * 128 + tid;
            int n = idx >> 5, dd = idx & 31;
            float val = Ps[n * D + dd] + Ps[NT * D + n * D + dd]
                      + __ldg(b2 + dd);
            float* gp = state + (size_t)(node_base + n) * ROW + toff + dd;
            *gp += dtv * val;
        }
    }
}

extern "C" void kernel_launch(void* const* d_in, const int* in_sizes, int n_in,
                              void* d_out, int out_size)
{
    const float* x    = (const float*)d_in[0];
    const float* tf   = (const float*)d_in[1];
    const float* W1q  = (const float*)d_in[2];
    const float* b1q  = (const float*)d_in[3];
    const float* W2q  = (const float*)d_in[4];
    const float* b2q  = (const float*)d_in[5];
    const float* W1p  = (const float*)d_in[6];
    const float* b1p  = (const float*)d_in[7];
    const float* W2p  = (const float*)d_in[8];
    const float* b2p  = (const float*)d_in[9];
    float* state = (float*)d_out;

    cudaMemcpyAsync(state, x, (size_t)out_size * sizeof(float),
                    cudaMemcpyDeviceToDevice);

    precompute_C_kernel<<<TOTAL / 128, 128>>>(x, W1q, b1q, 0);
    precompute_C_kernel<<<TOTAL / 128, 128>>>(x, W1p, b1p, 1);

    const int blocks = TOTAL / NT;   // 1024
    const float DT = 0.25f;

    for (int k = 0; k < 18; k++) {
        float tsq = (k == 0) ? 0.0f : (0.125f + (k - 1) * DT);
        float dmq = (k == 0) ? 0.125f : DT;
        half_step_kernel<<<blocks, 128>>>(
            state, tf, W1q, W2q, b2q, /*which=*/0,
            /*zoff=*/D, /*toff=*/0, tsq, dmq);

        float tsp = k * DT;
        half_step_kernel<<<blocks, 128>>>(
            state, tf, W1p, W2p, b2p, /*which=*/1,
            /*zoff=*/0, /*toff=*/D, tsp, DT);
    }
    (void)in_sizes; (void)n_in;
}